// round 11
// baseline (speedup 1.0000x reference)
#include <cuda_runtime.h>

// PlasticNet: T=64 steps, B=32, I=128, H=256, clip=2.0
// out = [ ys (T*B*H) | h_f (B*H) | hebb_f (B*H*H) ]  float32
//
// Single kernel: 32 clusters of 4 CTAs (one per sample). CTA c owns
// presynaptic rows [c*64, c*64+64); thread t owns column t.
// Prologue: CTA c computes xwi = x@Wi+bi for steps [16c,16c+16) of its sample
// (cross-CTA g_xwi accesses are coherent __ldcg, ordered by the init barrier).
// hebb kept in saturated space hbs=(hebb+2)/4 in [0,1]: clip = free .sat on
// FFMA. rec uses w'=w-2a, a'=4a: w+a*hebb = w'+a'*hbs.
// Per step: push rec partials into the 3 peers' SMEM, __syncthreads, then
// threads 0-3 issue ONE parallel release-arrive each to the 4 cluster CTAs'
// mbarriers (count=4, double-buffered by parity); consumers acquire-wait.

static constexpr int kT = 64;
static constexpr int kB = 32;
static constexpr int kI = 128;
static constexpr int kH = 256;
static constexpr int kRows = 64;
static constexpr int kNCTA = kB * 4;
static constexpr int kThreads = 256;

typedef unsigned long long ull;

__device__ float g_xwi[kT * kB * kH];              // x@Wi + bi

// ---------------------------------------------------------------------------
// PTX helpers
// ---------------------------------------------------------------------------
__device__ __forceinline__ unsigned smem_u32(const void* p) {
    return (unsigned)__cvta_generic_to_shared(p);
}
__device__ __forceinline__ unsigned mapa_u32(unsigned addr, unsigned rank) {
    unsigned o;
    asm("mapa.shared::cluster.u32 %0, %1, %2;" : "=r"(o) : "r"(addr), "r"(rank));
    return o;
}
__device__ __forceinline__ void st_cluster_f32(unsigned addr, float v) {
    asm volatile("st.shared::cluster.f32 [%0], %1;" :: "r"(addr), "f"(v) : "memory");
}
__device__ __forceinline__ void mbar_init(unsigned addr, unsigned cnt) {
    asm volatile("mbarrier.init.shared.b64 [%0], %1;" :: "r"(addr), "r"(cnt) : "memory");
}
__device__ __forceinline__ void mbar_arrive_rel_cluster(unsigned addr) {
    asm volatile("mbarrier.arrive.release.cluster.shared::cluster.b64 _, [%0];"
                 :: "r"(addr) : "memory");
}
__device__ __forceinline__ void mbar_wait_acq_cluster(unsigned addr, unsigned phase) {
    unsigned done;
    asm volatile(
        "{\n\t.reg .pred p;\n\t"
        "mbarrier.try_wait.parity.acquire.cluster.shared::cta.b64 p, [%1], %2;\n\t"
        "selp.b32 %0, 1, 0, p;\n\t}"
        : "=r"(done) : "r"(addr), "r"(phase) : "memory");
    if (!done) {
        asm volatile(
            "{\n\t.reg .pred P1;\n\t"
            "W_%=:\n\t"
            "mbarrier.try_wait.parity.acquire.cluster.shared::cta.b64 P1, [%0], %1, 0x989680;\n\t"
            "@P1 bra.uni D_%=;\n\t"
            "bra.uni W_%=;\n\t"
            "D_%=:\n\t}"
            :: "r"(addr), "r"(phase) : "memory");
    }
}
__device__ __forceinline__ void cluster_sync_all() {
    asm volatile("barrier.cluster.arrive.aligned;" ::: "memory");
    asm volatile("barrier.cluster.wait.aligned;" ::: "memory");
}

// ---- f32x2 packed math ----
__device__ __forceinline__ ull pack2(float lo, float hi) {
    ull r; asm("mov.b64 %0, {%1, %2};" : "=l"(r) : "f"(lo), "f"(hi)); return r;
}
__device__ __forceinline__ void unpack2(ull v, float& lo, float& hi) {
    asm("mov.b64 {%0, %1}, %2;" : "=f"(lo), "=f"(hi) : "l"(v));
}
__device__ __forceinline__ ull fma2(ull a, ull b, ull c) {
    ull d; asm("fma.rn.f32x2 %0, %1, %2, %3;" : "=l"(d) : "l"(a), "l"(b), "l"(c));
    return d;
}
// saturating scalar fma: clamps result to [0,1] as a free output modifier
__device__ __forceinline__ float fma_sat(float a, float b, float c) {
    float d; asm("fma.rn.sat.f32 %0, %1, %2, %3;" : "=f"(d) : "f"(a), "f"(b), "f"(c));
    return d;
}

// ---------------------------------------------------------------------------
__global__ void __launch_bounds__(kThreads, 1) __cluster_dims__(4, 1, 1)
plastic_kernel(const float* __restrict__ x,
               const float* __restrict__ Wi,
               const float* __restrict__ bi,
               const float* __restrict__ w,
               const float* __restrict__ alpha,
               const float* __restrict__ Wm,
               const float* __restrict__ bm,
               const float* __restrict__ Wf,
               const float* __restrict__ bf,
               float* __restrict__ out) {
    const int b = blockIdx.x >> 2;
    const int c = blockIdx.x & 3;      // cluster ctarank
    const int t = threadIdx.x;
    const int lane = t & 31;
    const int wid = t >> 5;
    const int i0 = c * kRows;

    __shared__ __align__(16) float hbuf[2][kH];       // h double buffer
    __shared__ __align__(16) float recv[2][4][kH];    // cluster partials, dbl buf
    __shared__ __align__(16) float wpart[8];          // per-warp eta partials
    __shared__ __align__(8) unsigned long long mbar[2];

    // ======== prologue: xwi for steps [16c, 16c+16) of sample b ========
    {
        float* xs = reinterpret_cast<float*>(recv);   // 16*128 floats = 8KB alias
        const float bi_t = __ldg(&bi[t]);
        const int s0 = c * 16;
        if (t < kI) {
#pragma unroll
            for (int s = 0; s < 16; ++s)
                xs[s * kI + t] = __ldg(&x[((s0 + s) * kB + b) * kI + t]);
        }
        if (t == 0) { mbar_init(smem_u32(&mbar[0]), 4); mbar_init(smem_u32(&mbar[1]), 4); }
        __syncthreads();
        float acc[16];
#pragma unroll
        for (int s = 0; s < 16; ++s) acc[s] = bi_t;
#pragma unroll 4
        for (int ib = 0; ib < kI; ib += 4) {
            const float q0 = __ldg(&Wi[(ib + 0) * kH + t]);
            const float q1 = __ldg(&Wi[(ib + 1) * kH + t]);
            const float q2 = __ldg(&Wi[(ib + 2) * kH + t]);
            const float q3 = __ldg(&Wi[(ib + 3) * kH + t]);
#pragma unroll
            for (int s = 0; s < 16; ++s) {
                const float4 xv = *reinterpret_cast<const float4*>(&xs[s * kI + ib]);
                acc[s] = fmaf(xv.w, q3, fmaf(xv.z, q2,
                         fmaf(xv.y, q1, fmaf(xv.x, q0, acc[s]))));
            }
        }
#pragma unroll
        for (int s = 0; s < 16; ++s)
            g_xwi[((s0 + s) * kB + b) * kH + t] = acc[s];
    }

    // ======== register state: rows i0+2j, i0+2j+1, column t ========
    // wv2 = (w - 2a) pair, av2 = (4a) pair, hbs = (hebb+2)/4 in [0,1]
    ull wv2[32], av2[32];
    float hbL[32], hbH[32];
#pragma unroll
    for (int j = 0; j < 32; ++j) {
        const float w0 = __ldg(&w[(i0 + 2 * j) * kH + t]);
        const float w1 = __ldg(&w[(i0 + 2 * j + 1) * kH + t]);
        const float a0 = __ldg(&alpha[(i0 + 2 * j) * kH + t]);
        const float a1 = __ldg(&alpha[(i0 + 2 * j + 1) * kH + t]);
        wv2[j] = pack2(fmaf(-2.f, a0, w0), fmaf(-2.f, a1, w1));
        av2[j] = pack2(4.f * a0, 4.f * a1);
        hbL[j] = 0.5f;   // hebb = 0
        hbH[j] = 0.5f;
    }
    const float wf_t = __ldg(&Wf[t]);
    const float bf_t = __ldg(&bf[t]);
    const float wm_t = __ldg(&Wm[t]);
    const float bm0 = __ldg(&bm[0]);

    hbuf[0][t] = 0.f;   // h_{-1} = 0
    __syncthreads();
    // orders: peers' smem + mbarriers live, AND all 4 CTAs' g_xwi stores
    // visible to subsequent coherent (__ldcg) loads within the cluster
    cluster_sync_all();

    // DSMEM push addresses (3 peers, both parities) and arrive targets.
    // Slot layout: recv[p][src_rank][t] in every CTA holds rank src's partial.
    unsigned pr_addr[2][3];
    unsigned my_arrive[2];             // thread t<4 arrives at rank t's mbar
#pragma unroll
    for (int p = 0; p < 2; ++p) {
        const unsigned lr = smem_u32(&recv[p][c][t]);
#pragma unroll
        for (int d = 1; d < 4; ++d)
            pr_addr[p][d - 1] = mapa_u32(lr, (unsigned)((c + d) & 3));
        my_arrive[p] = mapa_u32(smem_u32(&mbar[p]), (unsigned)(t & 3));
    }
    // peer slot pointers for hsum (3 peers)
    const float* peer0[2]; const float* peer1[2]; const float* peer2[2];
#pragma unroll
    for (int p = 0; p < 2; ++p) {
        peer0[p] = &recv[p][(c + 1) & 3][t];
        peer1[p] = &recv[p][(c + 2) & 3][t];
        peer2[p] = &recv[p][(c + 3) & 3][t];
    }

    float* __restrict__ ys = out;
    float* __restrict__ hf = out + kT * kB * kH;
    float* __restrict__ hebbf = out + kT * kB * kH + kB * kH;

    // step 0: h_{-1}=0 -> rec=0 -> h = tanh(xwi[0])  (coherent load)
    float h_cur = tanhf(__ldcg(&g_xwi[b * kH + t]));

    for (int step = 0; step < kT; ++step) {
        const int par = step & 1;
        const float* __restrict__ hp = hbuf[par];        // h_{step-1}
        float* __restrict__ hn = hbuf[par ^ 1];          // h_step

        // prefetch next step's xwi early (coherent; hides L2 latency)
        float xw_next = 0.f;
        if (step < kT - 1)
            xw_next = __ldcg(&g_xwi[((step + 1) * kB + b) * kH + t]);

        hn[t] = h_cur;
        // eta partial: warp-level reduce of h.Wm, pre-sync
        float s = h_cur * wm_t;
#pragma unroll
        for (int off = 16; off; off >>= 1)
            s += __shfl_xor_sync(0xffffffffu, s, off);
        if (lane == 0) wpart[wid] = s;
        if (c == 0) ys[(step * kB + b) * kH + t] = h_cur;
        __syncthreads();

        // ---- eta = tanh(h . Wm + bm) ----
        const float4 wp0 = *reinterpret_cast<const float4*>(&wpart[0]);
        const float4 wp1 = *reinterpret_cast<const float4*>(&wpart[4]);
        const float eta = tanhf(((wp0.x + wp0.y) + (wp0.z + wp0.w)) +
                                ((wp1.x + wp1.y) + (wp1.z + wp1.w)) + bm0);
        const float v = fmaf(eta, wf_t, bf_t) * h_cur;    // me_t * h_t
        const float v4 = 0.25f * v;                       // exact scale

        // ---- fused sweep: hbs = sat(hbs + v4*hp), pr += hn*(w' + a'*hbs) ----
        ull prA = 0ull, prB = 0ull;
#pragma unroll
        for (int jj = 0; jj < 16; ++jj) {
            const float4 hp4 = *reinterpret_cast<const float4*>(&hp[i0 + 4 * jj]);
            const float4 hn4 = *reinterpret_cast<const float4*>(&hn[i0 + 4 * jj]);
            const int j = 2 * jj;
            hbL[j]     = fma_sat(v4, hp4.x, hbL[j]);
            hbH[j]     = fma_sat(v4, hp4.y, hbH[j]);
            hbL[j + 1] = fma_sat(v4, hp4.z, hbL[j + 1]);
            hbH[j + 1] = fma_sat(v4, hp4.w, hbH[j + 1]);
            prA = fma2(pack2(hn4.x, hn4.y),
                       fma2(av2[j], pack2(hbL[j], hbH[j]), wv2[j]), prA);
            prB = fma2(pack2(hn4.z, hn4.w),
                       fma2(av2[j + 1], pack2(hbL[j + 1], hbH[j + 1]), wv2[j + 1]), prB);
        }

        if (step < kT - 1) {
            float pa, pb, pc_, pd;
            unpack2(prA, pa, pb);
            unpack2(prB, pc_, pd);
            const float pr = (pa + pb) + (pc_ + pd);
            const int np = par ^ 1;
            // push own partial to the 3 peers (own stays in register)
            st_cluster_f32(pr_addr[np][0], pr);
            st_cluster_f32(pr_addr[np][1], pr);
            st_cluster_f32(pr_addr[np][2], pr);
            __syncthreads();                 // all CTA pushes done (HB chain)
            if (t < 4)                       // 4 PARALLEL release-arrives
                mbar_arrive_rel_cluster(my_arrive[np]);
            mbar_wait_acq_cluster(smem_u32(&mbar[np]), (unsigned)((step >> 1) & 1));
            const float hsum = (pr + *peer0[np]) + (*peer1[np] + *peer2[np]);
            h_cur = tanhf(xw_next + hsum);
        }
    }

    // ---- final outputs (hebb = 4*hbs - 2) ----
    if (c == 0) hf[b * kH + t] = h_cur;    // h at step T-1
#pragma unroll
    for (int j = 0; j < 32; ++j) {
        hebbf[(size_t)b * kH * kH + (i0 + 2 * j) * kH + t] =
            fmaf(4.f, hbL[j], -2.f);
        hebbf[(size_t)b * kH * kH + (i0 + 2 * j + 1) * kH + t] =
            fmaf(4.f, hbH[j], -2.f);
    }
}

// ---------------------------------------------------------------------------
extern "C" void kernel_launch(void* const* d_in, const int* in_sizes, int n_in,
                              void* d_out, int out_size) {
    const float* x     = (const float*)d_in[0];
    const float* Wi    = (const float*)d_in[1];
    const float* bi    = (const float*)d_in[2];
    const float* w     = (const float*)d_in[3];
    const float* alpha = (const float*)d_in[4];
    const float* Wm    = (const float*)d_in[5];
    const float* bm    = (const float*)d_in[6];
    const float* Wf    = (const float*)d_in[7];
    const float* bf    = (const float*)d_in[8];
    float* out = (float*)d_out;

    plastic_kernel<<<kNCTA, kThreads>>>(x, Wi, bi, w, alpha, Wm, bm, Wf, bf, out);
}

// round 12
// speedup vs baseline: 1.2142x; 1.2142x over previous
#include <cuda_runtime.h>

// PlasticNet: T=64 steps, B=32, I=128, H=256, clip=2.0
// out = [ ys (T*B*H) | h_f (B*H) | hebb_f (B*H*H) ]  float32
//
// Single kernel: 32 clusters of 4 CTAs (one per sample). CTA c owns
// presynaptic rows [c*64, c*64+64); thread t owns column t.
// Prologue: CTA c computes xwi = x@Wi+bi for steps [16c,16c+16) (coherent
// __ldcg cross-CTA, ordered by the one-time init cluster barrier).
// hebb in saturated space hbs=(hebb+2)/4: clip = free .sat on FFMA.
// Steady-state sync: NO barriers. Each thread pushes (tag=step, partial) as
// one 8B st.shared::cluster.b64 into the 3 peers' SMEM; consumers spin on
// LOCAL smem until the tag matches. Slot reuse (parity) is causally safe.

static constexpr int kT = 64;
static constexpr int kB = 32;
static constexpr int kI = 128;
static constexpr int kH = 256;
static constexpr int kRows = 64;
static constexpr int kNCTA = kB * 4;
static constexpr int kThreads = 256;

typedef unsigned long long ull;

__device__ float g_xwi[kT * kB * kH];              // x@Wi + bi

// ---------------------------------------------------------------------------
// PTX helpers
// ---------------------------------------------------------------------------
__device__ __forceinline__ unsigned smem_u32(const void* p) {
    return (unsigned)__cvta_generic_to_shared(p);
}
__device__ __forceinline__ unsigned mapa_u32(unsigned addr, unsigned rank) {
    unsigned o;
    asm("mapa.shared::cluster.u32 %0, %1, %2;" : "=r"(o) : "r"(addr), "r"(rank));
    return o;
}
__device__ __forceinline__ void st_cluster_u64(unsigned addr, ull v) {
    asm volatile("st.shared::cluster.b64 [%0], %1;" :: "r"(addr), "l"(v) : "memory");
}
__device__ __forceinline__ ull ld_vol_smem_u64(unsigned addr) {
    ull v;
    asm volatile("ld.volatile.shared.b64 %0, [%1];" : "=l"(v) : "r"(addr));
    return v;
}
// spin on a local smem slot until its high word == tag; return value (low word)
__device__ __forceinline__ float wait_slot(unsigned addr, unsigned tag) {
    ull v = ld_vol_smem_u64(addr);
    while ((unsigned)(v >> 32) != tag) v = ld_vol_smem_u64(addr);
    return __uint_as_float((unsigned)v);
}
__device__ __forceinline__ void cluster_sync_all() {
    asm volatile("barrier.cluster.arrive.aligned;" ::: "memory");
    asm volatile("barrier.cluster.wait.aligned;" ::: "memory");
}

// ---- f32x2 packed math ----
__device__ __forceinline__ ull pack2(float lo, float hi) {
    ull r; asm("mov.b64 %0, {%1, %2};" : "=l"(r) : "f"(lo), "f"(hi)); return r;
}
__device__ __forceinline__ void unpack2(ull v, float& lo, float& hi) {
    asm("mov.b64 {%0, %1}, %2;" : "=f"(lo), "=f"(hi) : "l"(v));
}
__device__ __forceinline__ ull fma2(ull a, ull b, ull c) {
    ull d; asm("fma.rn.f32x2 %0, %1, %2, %3;" : "=l"(d) : "l"(a), "l"(b), "l"(c));
    return d;
}
// saturating scalar fma: clamps result to [0,1] as a free output modifier
__device__ __forceinline__ float fma_sat(float a, float b, float c) {
    float d; asm("fma.rn.sat.f32 %0, %1, %2, %3;" : "=f"(d) : "f"(a), "f"(b), "f"(c));
    return d;
}

// ---------------------------------------------------------------------------
__global__ void __launch_bounds__(kThreads, 1) __cluster_dims__(4, 1, 1)
plastic_kernel(const float* __restrict__ x,
               const float* __restrict__ Wi,
               const float* __restrict__ bi,
               const float* __restrict__ w,
               const float* __restrict__ alpha,
               const float* __restrict__ Wm,
               const float* __restrict__ bm,
               const float* __restrict__ Wf,
               const float* __restrict__ bf,
               float* __restrict__ out) {
    const int b = blockIdx.x >> 2;
    const int c = blockIdx.x & 3;      // cluster ctarank
    const int t = threadIdx.x;
    const int lane = t & 31;
    const int wid = t >> 5;
    const int i0 = c * kRows;

    __shared__ __align__(16) float hbuf[2][kH];       // h double buffer
    __shared__ __align__(16) ull slots[2][4][kH];     // (tag,value) msgs, dbl buf
    __shared__ __align__(16) float wpart[8];          // per-warp eta partials

    // ======== prologue: xwi for steps [16c, 16c+16) of sample b ========
    {
        float* xs = reinterpret_cast<float*>(slots);  // 8KB scratch alias
        const float bi_t = __ldg(&bi[t]);
        const int s0 = c * 16;
        if (t < kI) {
#pragma unroll
            for (int s = 0; s < 16; ++s)
                xs[s * kI + t] = __ldg(&x[((s0 + s) * kB + b) * kI + t]);
        }
        __syncthreads();
        float acc[16];
#pragma unroll
        for (int s = 0; s < 16; ++s) acc[s] = bi_t;
#pragma unroll 4
        for (int ib = 0; ib < kI; ib += 4) {
            const float q0 = __ldg(&Wi[(ib + 0) * kH + t]);
            const float q1 = __ldg(&Wi[(ib + 1) * kH + t]);
            const float q2 = __ldg(&Wi[(ib + 2) * kH + t]);
            const float q3 = __ldg(&Wi[(ib + 3) * kH + t]);
#pragma unroll
            for (int s = 0; s < 16; ++s) {
                const float4 xv = *reinterpret_cast<const float4*>(&xs[s * kI + ib]);
                acc[s] = fmaf(xv.w, q3, fmaf(xv.z, q2,
                         fmaf(xv.y, q1, fmaf(xv.x, q0, acc[s]))));
            }
        }
#pragma unroll
        for (int s = 0; s < 16; ++s)
            g_xwi[((s0 + s) * kB + b) * kH + t] = acc[s];
    }
    __syncthreads();   // xs scratch reads done before slot tag init below

    // ======== register state: rows i0+2j, i0+2j+1, column t ========
    // wv2 = (w - 2a) pair, av2 = (4a) pair, hbs = (hebb+2)/4 in [0,1]
    ull wv2[32], av2[32];
    float hbL[32], hbH[32];
#pragma unroll
    for (int j = 0; j < 32; ++j) {
        const float w0 = __ldg(&w[(i0 + 2 * j) * kH + t]);
        const float w1 = __ldg(&w[(i0 + 2 * j + 1) * kH + t]);
        const float a0 = __ldg(&alpha[(i0 + 2 * j) * kH + t]);
        const float a1 = __ldg(&alpha[(i0 + 2 * j + 1) * kH + t]);
        wv2[j] = pack2(fmaf(-2.f, a0, w0), fmaf(-2.f, a1, w1));
        av2[j] = pack2(4.f * a0, 4.f * a1);
        hbL[j] = 0.5f;   // hebb = 0
        hbH[j] = 0.5f;
    }
    const float wf_t = __ldg(&Wf[t]);
    const float bf_t = __ldg(&bf[t]);
    const float wm_t = __ldg(&Wm[t]);
    const float bm0 = __ldg(&bm[0]);

    // invalid tags everywhere (0xFFFFFFFF != any step)
#pragma unroll
    for (int p = 0; p < 2; ++p)
#pragma unroll
        for (int r = 0; r < 4; ++r)
            slots[p][r][t] = 0xFFFFFFFF00000000ull;
    hbuf[0][t] = 0.f;   // h_{-1} = 0
    __syncthreads();
    // one-time barrier: peers' smem live, g_xwi stores visible to __ldcg
    cluster_sync_all();

    // push addresses (3 peers, both parities) + local spin addresses
    unsigned pr_addr[2][3], sl_addr[2][3];
#pragma unroll
    for (int p = 0; p < 2; ++p) {
        const unsigned lr = smem_u32(&slots[p][c][t]);
#pragma unroll
        for (int d = 1; d < 4; ++d) {
            pr_addr[p][d - 1] = mapa_u32(lr, (unsigned)((c + d) & 3));
            sl_addr[p][d - 1] = smem_u32(&slots[p][(c + d) & 3][t]);
        }
    }

    float* __restrict__ ys = out;
    float* __restrict__ hf = out + kT * kB * kH;
    float* __restrict__ hebbf = out + kT * kB * kH + kB * kH;

    // step 0: h_{-1}=0 -> rec=0 -> h = tanh(xwi[0])  (coherent load)
    float h_cur = tanhf(__ldcg(&g_xwi[b * kH + t]));

    for (int step = 0; step < kT; ++step) {
        const int par = step & 1;
        const float* __restrict__ hp = hbuf[par];        // h_{step-1}
        float* __restrict__ hn = hbuf[par ^ 1];          // h_step

        // prefetch next step's xwi early (coherent; hides L2 latency)
        float xw_next = 0.f;
        if (step < kT - 1)
            xw_next = __ldcg(&g_xwi[((step + 1) * kB + b) * kH + t]);

        hn[t] = h_cur;
        // eta partial: warp-level reduce of h.Wm, pre-sync
        float s = h_cur * wm_t;
#pragma unroll
        for (int off = 16; off; off >>= 1)
            s += __shfl_xor_sync(0xffffffffu, s, off);
        if (lane == 0) wpart[wid] = s;
        if (c == 0) ys[(step * kB + b) * kH + t] = h_cur;
        __syncthreads();

        // ---- eta = tanh(h . Wm + bm) ----
        const float4 wp0 = *reinterpret_cast<const float4*>(&wpart[0]);
        const float4 wp1 = *reinterpret_cast<const float4*>(&wpart[4]);
        const float eta = tanhf(((wp0.x + wp0.y) + (wp0.z + wp0.w)) +
                                ((wp1.x + wp1.y) + (wp1.z + wp1.w)) + bm0);
        const float v = fmaf(eta, wf_t, bf_t) * h_cur;    // me_t * h_t
        const float v4 = 0.25f * v;                       // exact scale

        // ---- fused sweep: hbs = sat(hbs + v4*hp), pr += hn*(w' + a'*hbs) ----
        ull prA = 0ull, prB = 0ull;
#pragma unroll
        for (int jj = 0; jj < 16; ++jj) {
            const float4 hp4 = *reinterpret_cast<const float4*>(&hp[i0 + 4 * jj]);
            const float4 hn4 = *reinterpret_cast<const float4*>(&hn[i0 + 4 * jj]);
            const int j = 2 * jj;
            hbL[j]     = fma_sat(v4, hp4.x, hbL[j]);
            hbH[j]     = fma_sat(v4, hp4.y, hbH[j]);
            hbL[j + 1] = fma_sat(v4, hp4.z, hbL[j + 1]);
            hbH[j + 1] = fma_sat(v4, hp4.w, hbH[j + 1]);
            prA = fma2(pack2(hn4.x, hn4.y),
                       fma2(av2[j], pack2(hbL[j], hbH[j]), wv2[j]), prA);
            prB = fma2(pack2(hn4.z, hn4.w),
                       fma2(av2[j + 1], pack2(hbL[j + 1], hbH[j + 1]), wv2[j + 1]), prB);
        }

        if (step < kT - 1) {
            float pa, pb, pc_, pd;
            unpack2(prA, pa, pb);
            unpack2(prB, pc_, pd);
            const float pr = (pa + pb) + (pc_ + pd);
            // push (tag=step, pr) as ONE 8B single-copy-atomic DSMEM store
            const ull msg = ((ull)(unsigned)step << 32) |
                            (ull)(unsigned)__float_as_uint(pr);
            st_cluster_u64(pr_addr[par][0], msg);
            st_cluster_u64(pr_addr[par][1], msg);
            st_cluster_u64(pr_addr[par][2], msg);
            // spin on LOCAL smem until all 3 peer tags match this step
            const float q0 = wait_slot(sl_addr[par][0], (unsigned)step);
            const float q1 = wait_slot(sl_addr[par][1], (unsigned)step);
            const float q2 = wait_slot(sl_addr[par][2], (unsigned)step);
            __syncthreads();   // all sweeps done before hp is overwritten
            h_cur = tanhf(xw_next + ((pr + q0) + (q1 + q2)));
        }
    }

    // ---- final outputs (hebb = 4*hbs - 2) ----
    if (c == 0) hf[b * kH + t] = h_cur;    // h at step T-1
#pragma unroll
    for (int j = 0; j < 32; ++j) {
        hebbf[(size_t)b * kH * kH + (i0 + 2 * j) * kH + t] =
            fmaf(4.f, hbL[j], -2.f);
        hebbf[(size_t)b * kH * kH + (i0 + 2 * j + 1) * kH + t] =
            fmaf(4.f, hbH[j], -2.f);
    }
}

// ---------------------------------------------------------------------------
extern "C" void kernel_launch(void* const* d_in, const int* in_sizes, int n_in,
                              void* d_out, int out_size) {
    const float* x     = (const float*)d_in[0];
    const float* Wi    = (const float*)d_in[1];
    const float* bi    = (const float*)d_in[2];
    const float* w     = (const float*)d_in[3];
    const float* alpha = (const float*)d_in[4];
    const float* Wm    = (const float*)d_in[5];
    const float* bm    = (const float*)d_in[6];
    const float* Wf    = (const float*)d_in[7];
    const float* bf    = (const float*)d_in[8];
    float* out = (float*)d_out;

    plastic_kernel<<<kNCTA, kThreads>>>(x, Wi, bi, w, alpha, Wm, bm, Wf, bf, out);
}